// round 7
// baseline (speedup 1.0000x reference)
#include <cuda_runtime.h>
#include <cuda_bf16.h>
#include <mma.h>
#include <cstdint>

using namespace nvcuda;

#define Bsz 64
#define Ssz 64
#define Hsz 1024
#define Vsz 32000
#define Tsz 40
#define NBLK 148
#define NTHR 256

// ---------------- scratch ----------------
__device__ float g_keysU[Bsz * Ssz * Hsz];          // 16 MB (includes ba+bu)
__device__ float g_emb[Tsz * Bsz * Hsz];            // 10 MB [t][b][h] (tf32-rounded)
__device__ float g_h[Bsz * Hsz];                    // exact fp32 hidden
__device__ float g_h32[Bsz * Hsz];                  // tf32-rounded copy for GEMMs
__device__ float g_q4[4][Bsz * Hsz];                // q split-K parts
__device__ float g_gh4[4][Bsz * 3 * Hsz];           // gh split-K parts
__device__ float g_gc4[4][Bsz * 3 * Hsz];           // gi ctx-half split-K parts
__device__ float g_giE[(size_t)Tsz * Bsz * 3 * Hsz];// 31.5 MB
__device__ float g_ctx[Bsz * Hsz];                  // tf32-rounded at store
__device__ __nv_bfloat16 g_hall[Tsz * Bsz * Hsz];   // 5 MB
__device__ __nv_bfloat16 g_wout[Vsz * Hsz];         // 65 MB
// tf32-RN pre-rounded operand copies
__device__ float g_enc32[Bsz * Ssz * Hsz];          // 16 MB
__device__ float g_Ua32[Hsz * Hsz];
__device__ float g_Wa32[Hsz * Hsz];
__device__ float g_Whh32[3 * Hsz * Hsz];
__device__ float g_Wih32[3 * Hsz * 2 * Hsz];
__device__ unsigned g_barcnt = 0;
__device__ unsigned g_bargen = 0;

// fast activations
__device__ __forceinline__ float tanh_fast(float x) {
    float y; asm("tanh.approx.f32 %0, %1;" : "=f"(y) : "f"(x)); return y;
}
__device__ __forceinline__ float ftanh(float x) {
    float e = __expf(2.f * x);
    return 1.f - __fdividef(2.f, e + 1.f);
}
__device__ __forceinline__ float fsigmoid(float x) {
    return __fdividef(1.f, 1.f + __expf(-x));
}
__device__ __forceinline__ float rnd32(float x) {   // tf32 round-to-nearest
    float y; asm("cvt.rna.tf32.f32 %0, %1;" : "=f"(y) : "f"(x)); return y;
}

// cp.async helpers
__device__ __forceinline__ void cp16(void* sdst, const void* gsrc) {
    unsigned s = (unsigned)__cvta_generic_to_shared(sdst);
    asm volatile("cp.async.cg.shared.global [%0], [%1], 16;\n" :: "r"(s), "l"(gsrc));
}
#define CP_COMMIT() asm volatile("cp.async.commit_group;\n")
#define CP_WAIT1()  asm volatile("cp.async.wait_group 1;\n")

// ---------------- init kernels ----------------
__global__ void k_round_tf32(const float* __restrict__ src, float* __restrict__ dst, int n4) {
    for (int i = blockIdx.x * blockDim.x + threadIdx.x; i < n4; i += gridDim.x * blockDim.x) {
        float4 v = ((const float4*)src)[i];
        v.x = rnd32(v.x); v.y = rnd32(v.y); v.z = rnd32(v.z); v.w = rnd32(v.w);
        ((float4*)dst)[i] = v;
    }
}

__global__ void k_embed(const int* __restrict__ target, const float* __restrict__ emb) {
    int t = blockIdx.x / Bsz, b = blockIdx.x % Bsz;
    int tok = (t == 0) ? 0 : target[b * Tsz + t - 1];
    const float4* src = (const float4*)(emb + (size_t)tok * Hsz);
    float4* dst = (float4*)(g_emb + ((size_t)t * Bsz + b) * Hsz);
    for (int j = threadIdx.x; j < Hsz / 4; j += blockDim.x) {
        float4 v = src[j];
        v.x = rnd32(v.x); v.y = rnd32(v.y); v.z = rnd32(v.z); v.w = rnd32(v.w);
        dst[j] = v;
    }
}

__global__ void k_init_h(const float* __restrict__ eh) {
    int i = blockIdx.x * blockDim.x + threadIdx.x;
    if (i < Bsz * Hsz) { g_h[i] = eh[i]; g_h32[i] = rnd32(eh[i]); }
}

__global__ void k_wout_conv(const float* __restrict__ W) {
    int n4 = Vsz * Hsz / 4;
    for (int i = blockIdx.x * blockDim.x + threadIdx.x; i < n4; i += gridDim.x * blockDim.x) {
        float4 v = ((const float4*)W)[i];
        ((__nv_bfloat162*)g_wout)[2 * i]     = __floats2bfloat162_rn(v.x, v.y);
        ((__nv_bfloat162*)g_wout)[2 * i + 1] = __floats2bfloat162_rn(v.z, v.w);
    }
}

__global__ void k_keysu_bias(const float* __restrict__ ba, const float* __restrict__ bu) {
    int total = Bsz * Ssz * Hsz;
    for (int i = blockIdx.x * blockDim.x + threadIdx.x; i < total; i += gridDim.x * blockDim.x) {
        int n = i & (Hsz - 1);
        g_keysU[i] += ba[n] + bu[n];
    }
}

// ---------------- tf32 64x128 tile GEMM, cp.async 3-stage, BK=16 ----------------
// 8 warps (2m x 4n), each warp 32x32 (2x2 fragments). 4 MMAs per 4 frag loads.
// smem: As[3][64][20] + Bs[3][128][20] = 46080 B.
__device__ __forceinline__ void gemm64x128(const float* __restrict__ A, int lda,
                                           const float* __restrict__ B, int ldb,
                                           float* __restrict__ C, int ldc,
                                           int kiters, float* sbuf) {
    float (*As)[64][20]  = (float(*)[64][20])sbuf;
    float (*Bs)[128][20] = (float(*)[128][20])(sbuf + 3 * 64 * 20);
    int tid = threadIdx.x;
    int ra = tid >> 2, ca = (tid & 3) << 2;   // A: one float4 per thread
    int rb = tid >> 1, cb = (tid & 1) << 3;   // B: two float4 per thread
    int warp = tid >> 5, wm = warp >> 2, wn = warp & 3;

    const float* Ap = A + (size_t)ra * lda + ca;
    const float* Bp = B + (size_t)rb * ldb + cb;

    wmma::fragment<wmma::accumulator, 16, 16, 8, float> acc[2][2];
#pragma unroll
    for (int i = 0; i < 2; i++)
#pragma unroll
        for (int j = 0; j < 2; j++) wmma::fill_fragment(acc[i][j], 0.f);

#pragma unroll
    for (int s = 0; s < 2; s++) {
        if (s < kiters) {
            cp16(&As[s][ra][ca], Ap + s * 16);
            cp16(&Bs[s][rb][cb], Bp + s * 16);
            cp16(&Bs[s][rb][cb + 4], Bp + s * 16 + 4);
        }
        CP_COMMIT();
    }

    int stg = 2;
    for (int it = 0; it < kiters; it++) {
        int cur = it % 3;
        CP_WAIT1();
        __syncthreads();
        if (it + 2 < kiters) {
            cp16(&As[stg][ra][ca], Ap + (it + 2) * 16);
            cp16(&Bs[stg][rb][cb], Bp + (it + 2) * 16);
            cp16(&Bs[stg][rb][cb + 4], Bp + (it + 2) * 16 + 4);
        }
        CP_COMMIT();
        stg++; if (stg == 3) stg = 0;
#pragma unroll
        for (int ks = 0; ks < 2; ks++) {
            wmma::fragment<wmma::matrix_a, 16, 16, 8, wmma::precision::tf32, wmma::row_major> af0, af1;
            wmma::fragment<wmma::matrix_b, 16, 16, 8, wmma::precision::tf32, wmma::col_major> bf0, bf1;
            wmma::load_matrix_sync(af0, &As[cur][wm * 32][ks * 8], 20);
            wmma::load_matrix_sync(af1, &As[cur][wm * 32 + 16][ks * 8], 20);
            wmma::load_matrix_sync(bf0, &Bs[cur][wn * 32][ks * 8], 20);
            wmma::load_matrix_sync(bf1, &Bs[cur][wn * 32 + 16][ks * 8], 20);
            wmma::mma_sync(acc[0][0], af0, bf0, acc[0][0]);
            wmma::mma_sync(acc[0][1], af0, bf1, acc[0][1]);
            wmma::mma_sync(acc[1][0], af1, bf0, acc[1][0]);
            wmma::mma_sync(acc[1][1], af1, bf1, acc[1][1]);
        }
    }
    __syncthreads();
#pragma unroll
    for (int i = 0; i < 2; i++)
#pragma unroll
        for (int j = 0; j < 2; j++)
            wmma::store_matrix_sync(C + (size_t)(wm * 32 + i * 16) * ldc + wn * 32 + j * 16,
                                    acc[i][j], ldc, wmma::mem_row_major);
}

// keysU = enc32 @ Ua32^T  : grid (8, 64)
__global__ __launch_bounds__(NTHR, 2) void k_gemm_keysu() {
    __shared__ float sbuf[11520];
    int m0 = blockIdx.y * 64, n0 = blockIdx.x * 128;
    gemm64x128(g_enc32 + (size_t)m0 * Hsz, Hsz, g_Ua32 + (size_t)n0 * Hsz, Hsz,
               g_keysU + (size_t)m0 * Hsz + n0, Hsz, 64, sbuf);
}

// gi_emb[t] = emb_t @ Wih32[:, 0:H]^T  : grid (24, 40)
__global__ __launch_bounds__(NTHR, 2) void k_gemm_giemb() {
    __shared__ float sbuf[11520];
    int n0 = blockIdx.x * 128;
    int t = blockIdx.y;
    gemm64x128(g_emb + (size_t)t * Bsz * Hsz, Hsz,
               g_Wih32 + (size_t)n0 * (2 * Hsz), 2 * Hsz,
               g_giE + (size_t)t * Bsz * 3 * Hsz + n0, 3 * Hsz, 64, sbuf);
}

// ---------------- persistent recurrence kernel ----------------
__global__ __launch_bounds__(NTHR, 1) void k_persist(
    const float* __restrict__ enc, const float* __restrict__ Va,
    const float* __restrict__ b_ih, const float* __restrict__ b_hh,
    float* __restrict__ out_attn, float* __restrict__ out_hid)
{
    __shared__ float sbuf[11520];
    __shared__ unsigned s_gen0;
    int tid = threadIdx.x;
    int bx = blockIdx.x;
    if (tid == 0) s_gen0 = *((volatile unsigned*)&g_bargen);
    __syncthreads();
    unsigned gen = s_gen0;

    auto gbar = [&]() {
        gen++;
        __syncthreads();
        if (tid == 0) {
            __threadfence();
            unsigned a = atomicAdd(&g_barcnt, 1u);
            if (a == NBLK - 1) {
                g_barcnt = 0;
                __threadfence();
                *((volatile unsigned*)&g_bargen) = gen;
            } else {
                while (*((volatile unsigned*)&g_bargen) != gen) __nanosleep(32);
                __threadfence();
            }
        }
        __syncthreads();
    };

    for (int t = 0; t < Tsz; t++) {
        // ---- Phase A: q = h@Wa^T (32 parts) | gh = h@W_hh^T (96 parts), K=256 each
        if (bx < 128) {
            if (bx < 32) {
                int jt = bx >> 2, kh = bx & 3, n0 = jt * 128;
                gemm64x128(g_h32 + kh * 256, Hsz,
                           g_Wa32 + (size_t)n0 * Hsz + kh * 256, Hsz,
                           g_q4[kh] + n0, Hsz, 16, sbuf);
            } else {
                int idx = bx - 32, jt = idx >> 2, kh = idx & 3, n0 = jt * 128;
                gemm64x128(g_h32 + kh * 256, Hsz,
                           g_Whh32 + (size_t)n0 * Hsz + kh * 256, Hsz,
                           g_gh4[kh] + n0, 3 * Hsz, 16, sbuf);
            }
        }
        gbar();

        // ---- Phase BC: scores + softmax + ctx ----
        if (bx < Bsz) {
            int b = bx;
            float* qs = sbuf;
            float* va = sbuf + 1024;
            float* sc = sbuf + 2048;
            float* ws = sbuf + 2112;
            for (int j = tid; j < Hsz; j += NTHR) {
                qs[j] = g_q4[0][b * Hsz + j] + g_q4[1][b * Hsz + j]
                      + g_q4[2][b * Hsz + j] + g_q4[3][b * Hsz + j];
                va[j] = Va[j];
            }
            __syncthreads();
            int w = tid >> 5, lane = tid & 31;
#pragma unroll
            for (int si = 0; si < 8; si++) {
                int s = w * 8 + si;
                const float* kp = g_keysU + (size_t)(b * Ssz + s) * Hsz;
                float acc = 0.f;
#pragma unroll 8
                for (int jj = 0; jj < 32; jj++) {
                    int j = lane + jj * 32;
                    acc += va[j] * tanh_fast(qs[j] + kp[j]);
                }
#pragma unroll
                for (int o = 16; o > 0; o >>= 1) acc += __shfl_xor_sync(0xffffffffu, acc, o);
                if (lane == 0) sc[s] = acc;
            }
            __syncthreads();
            if (w == 0) {
                float v0 = sc[lane], v1 = sc[lane + 32];
                float m = fmaxf(v0, v1);
#pragma unroll
                for (int o = 16; o > 0; o >>= 1) m = fmaxf(m, __shfl_xor_sync(0xffffffffu, m, o));
                float e0 = __expf(v0 - m), e1 = __expf(v1 - m);
                float ssum = e0 + e1;
#pragma unroll
                for (int o = 16; o > 0; o >>= 1) ssum += __shfl_xor_sync(0xffffffffu, ssum, o);
                float inv = __fdividef(1.f, ssum);
                ws[lane] = e0 * inv;
                ws[lane + 32] = e1 * inv;
            }
            __syncthreads();
            if (tid < Ssz) out_attn[(size_t)b * Tsz * Ssz + t * Ssz + tid] = ws[tid];
            float c0 = 0.f, c1 = 0.f, c2 = 0.f, c3 = 0.f;
            const float* ep = enc + (size_t)b * Ssz * Hsz + tid;
#pragma unroll 4
            for (int s = 0; s < Ssz; s++) {
                float wv = ws[s];
                const float* row = ep + (size_t)s * Hsz;
                c0 += wv * row[0];
                c1 += wv * row[256];
                c2 += wv * row[512];
                c3 += wv * row[768];
            }
            g_ctx[b * Hsz + tid]       = rnd32(c0);
            g_ctx[b * Hsz + tid + 256] = rnd32(c1);
            g_ctx[b * Hsz + tid + 512] = rnd32(c2);
            g_ctx[b * Hsz + tid + 768] = rnd32(c3);
        }
        gbar();

        // ---- Phase D: gi_ctx = ctx @ W_ih[:, H:2H]^T  (96 parts, K=256)
        if (bx < 96) {
            int jt = bx >> 2, kh = bx & 3, n0 = jt * 128;
            gemm64x128(g_ctx + kh * 256, Hsz,
                       g_Wih32 + (size_t)n0 * (2 * Hsz) + Hsz + kh * 256, 2 * Hsz,
                       g_gc4[kh] + n0, 3 * Hsz, 16, sbuf);
        }
        gbar();

        // ---- Phase E: gates + h update ----
        {
            const float* giE = g_giE + (size_t)t * Bsz * 3 * Hsz;
            for (int i = bx * NTHR + tid; i < Bsz * Hsz; i += NBLK * NTHR) {
                int b = i >> 10, j = i & (Hsz - 1);
                size_t base3 = (size_t)b * 3 * Hsz;
                float ir = giE[base3 + j] + b_ih[j];
                float iz = giE[base3 + Hsz + j] + b_ih[Hsz + j];
                float in = giE[base3 + 2 * Hsz + j] + b_ih[2 * Hsz + j];
                float hr = b_hh[j];
                float hz = b_hh[Hsz + j];
                float hn = b_hh[2 * Hsz + j];
#pragma unroll
                for (int kh = 0; kh < 4; kh++) {
                    ir += g_gc4[kh][base3 + j];
                    iz += g_gc4[kh][base3 + Hsz + j];
                    in += g_gc4[kh][base3 + 2 * Hsz + j];
                    hr += g_gh4[kh][base3 + j];
                    hz += g_gh4[kh][base3 + Hsz + j];
                    hn += g_gh4[kh][base3 + 2 * Hsz + j];
                }
                float rr = fsigmoid(ir + hr);
                float zz = fsigmoid(iz + hz);
                float nn = ftanh(in + rr * hn);
                float hp = g_h[i];
                float hnew = (1.f - zz) * nn + zz * hp;
                g_h[i] = hnew;
                g_h32[i] = rnd32(hnew);
                g_hall[((size_t)t * Bsz + b) * Hsz + j] = __float2bfloat16(hnew);
            }
        }
        gbar();
    }

    for (int i = bx * NTHR + tid; i < Bsz * Hsz; i += NBLK * NTHR)
        out_hid[i] = g_h[i];
}

// ---------------- batched output projection: logits = Hall @ Wout^T + b_out ----------------
// bf16 wmma, block tile 128x128, BK=32, 8 warps (2x4), double-buffered smem
__global__ __launch_bounds__(256) void k_gemm_out(const float* __restrict__ b_out,
                                                  float* __restrict__ out) {
    const int K = Hsz;
    __shared__ __nv_bfloat16 As[2][128 * 40];
    __shared__ __nv_bfloat16 Bs[2][128 * 40];
    int m0 = blockIdx.y * 128, n0 = blockIdx.x * 128;
    int tid = threadIdx.x;
    int warp = tid >> 5, lane = tid & 31;
    int wm = warp >> 2, wn = warp & 3;
    int lrow = tid >> 2;
    int kch = (tid & 3) * 8;

    wmma::fragment<wmma::accumulator, 16, 16, 16, float> acc[4][2];
#pragma unroll
    for (int i = 0; i < 4; i++)
#pragma unroll
        for (int j = 0; j < 2; j++) wmma::fill_fragment(acc[i][j], 0.f);

    const __nv_bfloat16* Ag = g_hall + (size_t)(m0 + lrow) * K + kch;
    const __nv_bfloat16* Bg = g_wout + (size_t)(n0 + lrow) * K + kch;

    uint4 ra0, ra1, rb0, rb1;
    ra0 = *(const uint4*)(Ag);            ra1 = *(const uint4*)(Ag + 64 * K);
    rb0 = *(const uint4*)(Bg);            rb1 = *(const uint4*)(Bg + 64 * K);
    *(uint4*)&As[0][lrow * 40 + kch] = ra0;
    *(uint4*)&As[0][(lrow + 64) * 40 + kch] = ra1;
    *(uint4*)&Bs[0][lrow * 40 + kch] = rb0;
    *(uint4*)&Bs[0][(lrow + 64) * 40 + kch] = rb1;
    __syncthreads();

    const int NKT = K / 32;
    for (int kt = 0; kt < NKT; kt++) {
        int cur = kt & 1, nxt = cur ^ 1;
        if (kt + 1 < NKT) {
            const __nv_bfloat16* a = Ag + (kt + 1) * 32;
            ra0 = *(const uint4*)(a);     ra1 = *(const uint4*)(a + 64 * K);
            const __nv_bfloat16* bp = Bg + (kt + 1) * 32;
            rb0 = *(const uint4*)(bp);    rb1 = *(const uint4*)(bp + 64 * K);
        }
#pragma unroll
        for (int ks = 0; ks < 2; ks++) {
            wmma::fragment<wmma::matrix_a, 16, 16, 16, __nv_bfloat16, wmma::row_major> af[4];
            wmma::fragment<wmma::matrix_b, 16, 16, 16, __nv_bfloat16, wmma::col_major> bf[2];
#pragma unroll
            for (int i = 0; i < 4; i++)
                wmma::load_matrix_sync(af[i], &As[cur][(wm * 64 + i * 16) * 40 + ks * 16], 40);
#pragma unroll
            for (int j = 0; j < 2; j++)
                wmma::load_matrix_sync(bf[j], &Bs[cur][(wn * 32 + j * 16) * 40 + ks * 16], 40);
#pragma unroll
            for (int i = 0; i < 4; i++)
#pragma unroll
                for (int j = 0; j < 2; j++)
                    wmma::mma_sync(acc[i][j], af[i], bf[j], acc[i][j]);
        }
        if (kt + 1 < NKT) {
            *(uint4*)&As[nxt][lrow * 40 + kch] = ra0;
            *(uint4*)&As[nxt][(lrow + 64) * 40 + kch] = ra1;
            *(uint4*)&Bs[nxt][lrow * 40 + kch] = rb0;
            *(uint4*)&Bs[nxt][(lrow + 64) * 40 + kch] = rb1;
        }
        __syncthreads();
    }

    float* stage = (float*)&As[0][0];
    float* sp = stage + warp * 320;
#pragma unroll
    for (int i = 0; i < 4; i++) {
#pragma unroll
        for (int j = 0; j < 2; j++) {
            wmma::store_matrix_sync(sp, acc[i][j], 20, wmma::mem_row_major);
            __syncwarp();
            int gr0 = m0 + wm * 64 + i * 16;
            int gc0 = n0 + wn * 32 + j * 16;
            for (int e = lane; e < 256; e += 32) {
                int r = e >> 4, cc = e & 15;
                int gr = gr0 + r, gc = gc0 + cc;
                int bb = gr & 63, tt = gr >> 6;
                out[(size_t)(bb * Tsz + tt) * Vsz + gc] = sp[r * 20 + cc] + b_out[gc];
            }
            __syncwarp();
        }
    }
}

// ---------------- in-place log_softmax (float4) ----------------
__global__ __launch_bounds__(256) void k_logsoftmax(float* __restrict__ out) {
    int row = blockIdx.x;
    float4* p4 = (float4*)(out + (size_t)row * Vsz);
    const int N4 = Vsz / 4;
    int tid = threadIdx.x;
    float m = -1e30f, s = 0.f;
    for (int j = tid; j < N4; j += 256) {
        float4 v = p4[j];
        float vm = fmaxf(fmaxf(v.x, v.y), fmaxf(v.z, v.w));
        if (vm > m) { s = s * __expf(m - vm); m = vm; }
        s += __expf(v.x - m) + __expf(v.y - m) + __expf(v.z - m) + __expf(v.w - m);
    }
    __shared__ float sm[256], ss[256];
    sm[tid] = m; ss[tid] = s;
    __syncthreads();
    for (int o = 128; o > 0; o >>= 1) {
        if (tid < o) {
            float m2 = sm[tid + o], s2 = ss[tid + o];
            float mm = fmaxf(sm[tid], m2);
            ss[tid] = ss[tid] * __expf(sm[tid] - mm) + s2 * __expf(m2 - mm);
            sm[tid] = mm;
        }
        __syncthreads();
    }
    float L = sm[0] + logf(ss[0]);
    for (int j = tid; j < N4; j += 256) {
        float4 v = p4[j];
        v.x -= L; v.y -= L; v.z -= L; v.w -= L;
        p4[j] = v;
    }
}

// ---------------- launch ----------------
extern "C" void kernel_launch(void* const* d_in, const int* in_sizes, int n_in,
                              void* d_out, int out_size) {
    const float* enc_out = (const float*)d_in[0];
    const float* enc_hid = (const float*)d_in[1];
    const int*   target  = (const int*)d_in[2];
    const float* embedding = (const float*)d_in[3];
    const float* Wa  = (const float*)d_in[4];
    const float* ba  = (const float*)d_in[5];
    const float* Ua  = (const float*)d_in[6];
    const float* bu  = (const float*)d_in[7];
    const float* Va  = (const float*)d_in[8];
    // d_in[9] = bv : softmax shift-invariant, unused
    const float* W_ih = (const float*)d_in[10];
    const float* W_hh = (const float*)d_in[11];
    const float* b_ih = (const float*)d_in[12];
    const float* b_hh = (const float*)d_in[13];
    const float* W_out = (const float*)d_in[14];
    const float* b_out = (const float*)d_in[15];

    float* out = (float*)d_out;
    float* out_dec  = out;                                        // [B,T,V]
    float* out_hid  = out + (size_t)Bsz * Tsz * Vsz;              // [1,B,H]
    float* out_attn = out_hid + (size_t)Bsz * Hsz;                // [B,T,S]

    // tf32-RN pre-rounded operand copies
    float *enc32, *Ua32, *Wa32, *Whh32, *Wih32;
    cudaGetSymbolAddress((void**)&enc32, g_enc32);
    cudaGetSymbolAddress((void**)&Ua32,  g_Ua32);
    cudaGetSymbolAddress((void**)&Wa32,  g_Wa32);
    cudaGetSymbolAddress((void**)&Whh32, g_Whh32);
    cudaGetSymbolAddress((void**)&Wih32, g_Wih32);
    k_round_tf32<<<1024, 256>>>(enc_out, enc32, Bsz * Ssz * Hsz / 4);
    k_round_tf32<<<512, 256>>>(Ua, Ua32, Hsz * Hsz / 4);
    k_round_tf32<<<512, 256>>>(Wa, Wa32, Hsz * Hsz / 4);
    k_round_tf32<<<1024, 256>>>(W_hh, Whh32, 3 * Hsz * Hsz / 4);
    k_round_tf32<<<1024, 256>>>(W_ih, Wih32, 3 * Hsz * 2 * Hsz / 4);

    k_embed<<<Tsz * Bsz, 256>>>(target, embedding);
    k_init_h<<<(Bsz * Hsz + 255) / 256, 256>>>(enc_hid);
    k_wout_conv<<<2048, 256>>>(W_out);
    {
        dim3 grid(Hsz / 128, (Bsz * Ssz) / 64);   // 8 x 64
        k_gemm_keysu<<<grid, NTHR>>>();
    }
    k_keysu_bias<<<4096, 256>>>(ba, bu);
    {
        dim3 grid(3 * Hsz / 128, Tsz);            // 24 x 40
        k_gemm_giemb<<<grid, NTHR>>>();
    }

    // full recurrence in one launch
    k_persist<<<NBLK, NTHR>>>(enc_out, Va, b_ih, b_hh, out_attn, out_hid);

    // output projection + log_softmax
    {
        dim3 grid(Vsz / 128, (Tsz * Bsz) / 128);  // 250 x 20
        k_gemm_out<<<grid, 256>>>(b_out, out_dec);
    }
    k_logsoftmax<<<Tsz * Bsz, 256>>>(out_dec);
}

// round 8
// speedup vs baseline: 1.0282x; 1.0282x over previous
#include <cuda_runtime.h>
#include <cuda_bf16.h>
#include <mma.h>
#include <cstdint>

using namespace nvcuda;

#define Bsz 64
#define Ssz 64
#define Hsz 1024
#define Vsz 32000
#define Tsz 40
#define NBLK 148
#define NTHR 256

// ---------------- scratch ----------------
__device__ float g_keysU[Bsz * Ssz * Hsz];          // 16 MB (bias added in persist)
__device__ float g_emb[Tsz * Bsz * Hsz];            // 10 MB [t][b][h] (tf32-rounded)
__device__ float g_h[Bsz * Hsz];                    // exact fp32 hidden
__device__ float g_h32[Bsz * Hsz];                  // tf32-rounded copy for GEMMs
__device__ float g_q4[4][Bsz * Hsz];                // q split-K parts
__device__ float g_gh4[4][Bsz * 3 * Hsz];           // gh split-K parts
__device__ float g_gc4[4][Bsz * 3 * Hsz];           // gi ctx-half split-K parts
__device__ float g_giE[(size_t)Tsz * Bsz * 3 * Hsz];// 31.5 MB
__device__ float g_ctx[Bsz * Hsz];                  // tf32-rounded at store
__device__ __nv_bfloat16 g_hall[Tsz * Bsz * Hsz];   // 5 MB
__device__ __nv_bfloat16 g_wout[Vsz * Hsz];         // 65 MB
// tf32-RN pre-rounded operand copies
__device__ float g_enc32[Bsz * Ssz * Hsz];          // 16 MB
__device__ float g_Ua32[Hsz * Hsz];
__device__ float g_Wa32[Hsz * Hsz];
__device__ float g_Whh32[3 * Hsz * Hsz];
__device__ float g_Wih32[3 * Hsz * 2 * Hsz];
__device__ unsigned g_barcnt = 0;
__device__ unsigned g_bargen = 0;

// fast activations
__device__ __forceinline__ float tanh_fast(float x) {
    float y; asm("tanh.approx.f32 %0, %1;" : "=f"(y) : "f"(x)); return y;
}
__device__ __forceinline__ float ftanh(float x) {
    float e = __expf(2.f * x);
    return 1.f - __fdividef(2.f, e + 1.f);
}
__device__ __forceinline__ float fsigmoid(float x) {
    return __fdividef(1.f, 1.f + __expf(-x));
}
__device__ __forceinline__ float rnd32(float x) {   // tf32 round-to-nearest
    float y; asm("cvt.rna.tf32.f32 %0, %1;" : "=f"(y) : "f"(x)); return y;
}

// cp.async helpers
__device__ __forceinline__ void cp16(void* sdst, const void* gsrc) {
    unsigned s = (unsigned)__cvta_generic_to_shared(sdst);
    asm volatile("cp.async.cg.shared.global [%0], [%1], 16;\n" :: "r"(s), "l"(gsrc));
}
#define CP_COMMIT() asm volatile("cp.async.commit_group;\n")
#define CP_WAIT1()  asm volatile("cp.async.wait_group 1;\n")
#define CP_WAIT2()  asm volatile("cp.async.wait_group 2;\n")

// ---------------- init kernels ----------------
// one kernel rounds all 5 fp32 operand tensors to tf32-RN copies
__global__ void k_round_all(const float* __restrict__ enc, const float* __restrict__ Ua,
                            const float* __restrict__ Wa, const float* __restrict__ Whh,
                            const float* __restrict__ Wih) {
    const int nEnc = Bsz * Ssz * Hsz / 4;            // 1048576
    const int nUa  = Hsz * Hsz / 4;                  // 262144
    const int nWhh = 3 * Hsz * Hsz / 4;              // 786432
    const int nWih = 3 * Hsz * 2 * Hsz / 4;          // 1572864
    const int e0 = nEnc, e1 = e0 + nUa, e2 = e1 + nUa, e3 = e2 + nWhh, e4 = e3 + nWih;
    for (int i = blockIdx.x * blockDim.x + threadIdx.x; i < e4; i += gridDim.x * blockDim.x) {
        const float4* src; float4* dst;
        if (i < e0)      { src = (const float4*)enc + i;        dst = (float4*)g_enc32 + i; }
        else if (i < e1) { src = (const float4*)Ua + (i - e0);  dst = (float4*)g_Ua32 + (i - e0); }
        else if (i < e2) { src = (const float4*)Wa + (i - e1);  dst = (float4*)g_Wa32 + (i - e1); }
        else if (i < e3) { src = (const float4*)Whh + (i - e2); dst = (float4*)g_Whh32 + (i - e2); }
        else             { src = (const float4*)Wih + (i - e3); dst = (float4*)g_Wih32 + (i - e3); }
        float4 v = *src;
        v.x = rnd32(v.x); v.y = rnd32(v.y); v.z = rnd32(v.z); v.w = rnd32(v.w);
        *dst = v;
    }
}

// embedding gather (tf32-rounded) + h init
__global__ void k_embed_init(const int* __restrict__ target, const float* __restrict__ emb,
                             const float* __restrict__ eh) {
    int bx = blockIdx.x;
    if (bx < Tsz * Bsz) {
        int t = bx / Bsz, b = bx % Bsz;
        int tok = (t == 0) ? 0 : target[b * Tsz + t - 1];
        const float4* src = (const float4*)(emb + (size_t)tok * Hsz);
        float4* dst = (float4*)(g_emb + ((size_t)t * Bsz + b) * Hsz);
        for (int j = threadIdx.x; j < Hsz / 4; j += blockDim.x) {
            float4 v = src[j];
            v.x = rnd32(v.x); v.y = rnd32(v.y); v.z = rnd32(v.z); v.w = rnd32(v.w);
            dst[j] = v;
        }
    } else {
        int i = (bx - Tsz * Bsz) * 256 + threadIdx.x;
        if (i < Bsz * Hsz) { g_h[i] = eh[i]; g_h32[i] = rnd32(eh[i]); }
    }
}

__global__ void k_wout_conv(const float* __restrict__ W) {
    int n4 = Vsz * Hsz / 4;
    for (int i = blockIdx.x * blockDim.x + threadIdx.x; i < n4; i += gridDim.x * blockDim.x) {
        float4 v = ((const float4*)W)[i];
        ((__nv_bfloat162*)g_wout)[2 * i]     = __floats2bfloat162_rn(v.x, v.y);
        ((__nv_bfloat162*)g_wout)[2 * i + 1] = __floats2bfloat162_rn(v.z, v.w);
    }
}

// ---------------- tf32 64x128 tile GEMM, cp.async 3-stage, BK=16 ----------------
__device__ __forceinline__ void gemm64x128(const float* __restrict__ A, int lda,
                                           const float* __restrict__ B, int ldb,
                                           float* __restrict__ C, int ldc,
                                           int kiters, float* sbuf) {
    float (*As)[64][20]  = (float(*)[64][20])sbuf;
    float (*Bs)[128][20] = (float(*)[128][20])(sbuf + 3 * 64 * 20);
    int tid = threadIdx.x;
    int ra = tid >> 2, ca = (tid & 3) << 2;
    int rb = tid >> 1, cb = (tid & 1) << 3;
    int warp = tid >> 5, wm = warp >> 2, wn = warp & 3;

    const float* Ap = A + (size_t)ra * lda + ca;
    const float* Bp = B + (size_t)rb * ldb + cb;

    wmma::fragment<wmma::accumulator, 16, 16, 8, float> acc[2][2];
#pragma unroll
    for (int i = 0; i < 2; i++)
#pragma unroll
        for (int j = 0; j < 2; j++) wmma::fill_fragment(acc[i][j], 0.f);

#pragma unroll
    for (int s = 0; s < 2; s++) {
        if (s < kiters) {
            cp16(&As[s][ra][ca], Ap + s * 16);
            cp16(&Bs[s][rb][cb], Bp + s * 16);
            cp16(&Bs[s][rb][cb + 4], Bp + s * 16 + 4);
        }
        CP_COMMIT();
    }

    int stg = 2;
    for (int it = 0; it < kiters; it++) {
        int cur = it % 3;
        CP_WAIT1();
        __syncthreads();
        if (it + 2 < kiters) {
            cp16(&As[stg][ra][ca], Ap + (it + 2) * 16);
            cp16(&Bs[stg][rb][cb], Bp + (it + 2) * 16);
            cp16(&Bs[stg][rb][cb + 4], Bp + (it + 2) * 16 + 4);
        }
        CP_COMMIT();
        stg++; if (stg == 3) stg = 0;
#pragma unroll
        for (int ks = 0; ks < 2; ks++) {
            wmma::fragment<wmma::matrix_a, 16, 16, 8, wmma::precision::tf32, wmma::row_major> af0, af1;
            wmma::fragment<wmma::matrix_b, 16, 16, 8, wmma::precision::tf32, wmma::col_major> bf0, bf1;
            wmma::load_matrix_sync(af0, &As[cur][wm * 32][ks * 8], 20);
            wmma::load_matrix_sync(af1, &As[cur][wm * 32 + 16][ks * 8], 20);
            wmma::load_matrix_sync(bf0, &Bs[cur][wn * 32][ks * 8], 20);
            wmma::load_matrix_sync(bf1, &Bs[cur][wn * 32 + 16][ks * 8], 20);
            wmma::mma_sync(acc[0][0], af0, bf0, acc[0][0]);
            wmma::mma_sync(acc[0][1], af0, bf1, acc[0][1]);
            wmma::mma_sync(acc[1][0], af1, bf0, acc[1][0]);
            wmma::mma_sync(acc[1][1], af1, bf1, acc[1][1]);
        }
    }
    __syncthreads();
#pragma unroll
    for (int i = 0; i < 2; i++)
#pragma unroll
        for (int j = 0; j < 2; j++)
            wmma::store_matrix_sync(C + (size_t)(wm * 32 + i * 16) * ldc + wn * 32 + j * 16,
                                    acc[i][j], ldc, wmma::mem_row_major);
}

// keysU = enc32 @ Ua32^T  : grid (8, 64)
__global__ __launch_bounds__(NTHR, 2) void k_gemm_keysu() {
    __shared__ float sbuf[11520];
    int m0 = blockIdx.y * 64, n0 = blockIdx.x * 128;
    gemm64x128(g_enc32 + (size_t)m0 * Hsz, Hsz, g_Ua32 + (size_t)n0 * Hsz, Hsz,
               g_keysU + (size_t)m0 * Hsz + n0, Hsz, 64, sbuf);
}

// gi_emb[t] = emb_t @ Wih32[:, 0:H]^T  : grid (24, 40)
__global__ __launch_bounds__(NTHR, 2) void k_gemm_giemb() {
    __shared__ float sbuf[11520];
    int n0 = blockIdx.x * 128;
    int t = blockIdx.y;
    gemm64x128(g_emb + (size_t)t * Bsz * Hsz, Hsz,
               g_Wih32 + (size_t)n0 * (2 * Hsz), 2 * Hsz,
               g_giE + (size_t)t * Bsz * 3 * Hsz + n0, 3 * Hsz, 64, sbuf);
}

// ---------------- persistent recurrence kernel ----------------
__global__ __launch_bounds__(NTHR, 1) void k_persist(
    const float* __restrict__ enc, const float* __restrict__ Va,
    const float* __restrict__ ba, const float* __restrict__ bu,
    const float* __restrict__ b_ih, const float* __restrict__ b_hh,
    float* __restrict__ out_attn, float* __restrict__ out_hid)
{
    __shared__ float sbuf[11520];
    __shared__ unsigned s_gen0;
    int tid = threadIdx.x;
    int bx = blockIdx.x;
    if (tid == 0) s_gen0 = *((volatile unsigned*)&g_bargen);
    __syncthreads();
    unsigned gen = s_gen0;

    auto gbar = [&]() {
        gen++;
        __syncthreads();
        if (tid == 0) {
            __threadfence();
            unsigned a = atomicAdd(&g_barcnt, 1u);
            if (a == NBLK - 1) {
                g_barcnt = 0;
                __threadfence();
                *((volatile unsigned*)&g_bargen) = gen;
            } else {
                while (*((volatile unsigned*)&g_bargen) != gen) __nanosleep(32);
                __threadfence();
            }
        }
        __syncthreads();
    };

    // pre-phase: fold attention biases into keysU (replaces k_keysu_bias launch)
    for (int i = bx * NTHR + tid; i < Bsz * Ssz * Hsz; i += NBLK * NTHR) {
        int n = i & (Hsz - 1);
        g_keysU[i] += ba[n] + bu[n];
    }
    gbar();

    for (int t = 0; t < Tsz; t++) {
        // ---- Phase A: q = h@Wa^T (32 parts) | gh = h@W_hh^T (96 parts), K=256 each
        if (bx < 128) {
            if (bx < 32) {
                int jt = bx >> 2, kh = bx & 3, n0 = jt * 128;
                gemm64x128(g_h32 + kh * 256, Hsz,
                           g_Wa32 + (size_t)n0 * Hsz + kh * 256, Hsz,
                           g_q4[kh] + n0, Hsz, 16, sbuf);
            } else {
                int idx = bx - 32, jt = idx >> 2, kh = idx & 3, n0 = jt * 128;
                gemm64x128(g_h32 + kh * 256, Hsz,
                           g_Whh32 + (size_t)n0 * Hsz + kh * 256, Hsz,
                           g_gh4[kh] + n0, 3 * Hsz, 16, sbuf);
            }
        }
        gbar();

        // ---- Phase BC: scores + softmax + ctx ----
        if (bx < Bsz) {
            int b = bx;
            float* qs = sbuf;
            float* va = sbuf + 1024;
            float* sc = sbuf + 2048;
            float* ws = sbuf + 2112;
            for (int j = tid; j < Hsz; j += NTHR) {
                qs[j] = g_q4[0][b * Hsz + j] + g_q4[1][b * Hsz + j]
                      + g_q4[2][b * Hsz + j] + g_q4[3][b * Hsz + j];
                va[j] = Va[j];
            }
            __syncthreads();
            int w = tid >> 5, lane = tid & 31;
#pragma unroll
            for (int si = 0; si < 8; si++) {
                int s = w * 8 + si;
                const float* kp = g_keysU + (size_t)(b * Ssz + s) * Hsz;
                float acc = 0.f;
#pragma unroll 8
                for (int jj = 0; jj < 32; jj++) {
                    int j = lane + jj * 32;
                    acc += va[j] * tanh_fast(qs[j] + kp[j]);
                }
#pragma unroll
                for (int o = 16; o > 0; o >>= 1) acc += __shfl_xor_sync(0xffffffffu, acc, o);
                if (lane == 0) sc[s] = acc;
            }
            __syncthreads();
            if (w == 0) {
                float v0 = sc[lane], v1 = sc[lane + 32];
                float m = fmaxf(v0, v1);
#pragma unroll
                for (int o = 16; o > 0; o >>= 1) m = fmaxf(m, __shfl_xor_sync(0xffffffffu, m, o));
                float e0 = __expf(v0 - m), e1 = __expf(v1 - m);
                float ssum = e0 + e1;
#pragma unroll
                for (int o = 16; o > 0; o >>= 1) ssum += __shfl_xor_sync(0xffffffffu, ssum, o);
                float inv = __fdividef(1.f, ssum);
                ws[lane] = e0 * inv;
                ws[lane + 32] = e1 * inv;
            }
            __syncthreads();
            if (tid < Ssz) out_attn[(size_t)b * Tsz * Ssz + t * Ssz + tid] = ws[tid];
            float c0 = 0.f, c1 = 0.f, c2 = 0.f, c3 = 0.f;
            const float* ep = enc + (size_t)b * Ssz * Hsz + tid;
#pragma unroll 4
            for (int s = 0; s < Ssz; s++) {
                float wv = ws[s];
                const float* row = ep + (size_t)s * Hsz;
                c0 += wv * row[0];
                c1 += wv * row[256];
                c2 += wv * row[512];
                c3 += wv * row[768];
            }
            g_ctx[b * Hsz + tid]       = rnd32(c0);
            g_ctx[b * Hsz + tid + 256] = rnd32(c1);
            g_ctx[b * Hsz + tid + 512] = rnd32(c2);
            g_ctx[b * Hsz + tid + 768] = rnd32(c3);
        }
        gbar();

        // ---- Phase D: gi_ctx = ctx @ W_ih[:, H:2H]^T  (96 parts, K=256)
        if (bx < 96) {
            int jt = bx >> 2, kh = bx & 3, n0 = jt * 128;
            gemm64x128(g_ctx + kh * 256, Hsz,
                       g_Wih32 + (size_t)n0 * (2 * Hsz) + Hsz + kh * 256, 2 * Hsz,
                       g_gc4[kh] + n0, 3 * Hsz, 16, sbuf);
        }
        gbar();

        // ---- Phase E: gates + h update ----
        {
            const float* giE = g_giE + (size_t)t * Bsz * 3 * Hsz;
            for (int i = bx * NTHR + tid; i < Bsz * Hsz; i += NBLK * NTHR) {
                int b = i >> 10, j = i & (Hsz - 1);
                size_t base3 = (size_t)b * 3 * Hsz;
                float ir = giE[base3 + j] + b_ih[j];
                float iz = giE[base3 + Hsz + j] + b_ih[Hsz + j];
                float in = giE[base3 + 2 * Hsz + j] + b_ih[2 * Hsz + j];
                float hr = b_hh[j];
                float hz = b_hh[Hsz + j];
                float hn = b_hh[2 * Hsz + j];
#pragma unroll
                for (int kh = 0; kh < 4; kh++) {
                    ir += g_gc4[kh][base3 + j];
                    iz += g_gc4[kh][base3 + Hsz + j];
                    in += g_gc4[kh][base3 + 2 * Hsz + j];
                    hr += g_gh4[kh][base3 + j];
                    hz += g_gh4[kh][base3 + Hsz + j];
                    hn += g_gh4[kh][base3 + 2 * Hsz + j];
                }
                float rr = fsigmoid(ir + hr);
                float zz = fsigmoid(iz + hz);
                float nn = ftanh(in + rr * hn);
                float hp = g_h[i];
                float hnew = (1.f - zz) * nn + zz * hp;
                g_h[i] = hnew;
                g_h32[i] = rnd32(hnew);
                g_hall[((size_t)t * Bsz + b) * Hsz + j] = __float2bfloat16(hnew);
            }
        }
        gbar();
    }

    for (int i = bx * NTHR + tid; i < Bsz * Hsz; i += NBLK * NTHR)
        out_hid[i] = g_h[i];
}

// ---------------- output projection: logits = Hall @ Wout^T + b_out ----------------
// bf16 wmma, 128x128 tile, BK=32, 4-stage cp.async pipeline, 80KB dynamic smem.
#define OUT_STAGE_B 10240   // 128 rows x 40 bf16 x 2B per operand stage
__global__ __launch_bounds__(256, 2) void k_gemm_out(const float* __restrict__ b_out,
                                                     float* __restrict__ out) {
    extern __shared__ char dyn[];
    char* sA = dyn;                        // 4 stages x 10240
    char* sB = dyn + 4 * OUT_STAGE_B;      // 4 stages x 10240
    const int K = Hsz;
    int m0 = blockIdx.y * 128, n0 = blockIdx.x * 128;
    int tid = threadIdx.x;
    int warp = tid >> 5, lane = tid & 31;
    int wm = warp >> 2, wn = warp & 3;

    const char* Ag = (const char*)(g_hall + (size_t)m0 * K);
    const char* Bg = (const char*)(g_wout + (size_t)n0 * K);

    // per-thread copy map: 512 16B-chunks per operand per stage; 2 chunks each
    int c0 = tid * 2;
    int rowA0 = c0 >> 2, off0 = (c0 & 3) * 16;
    int rowA1 = (c0 + 1) >> 2, off1 = ((c0 + 1) & 3) * 16;

    auto load_stage = [&](int kt, int s) {
        char* dA = sA + s * OUT_STAGE_B;
        char* dB = sB + s * OUT_STAGE_B;
        const char* a0 = Ag + (size_t)rowA0 * (K * 2) + kt * 64 + off0;
        const char* a1 = Ag + (size_t)rowA1 * (K * 2) + kt * 64 + off1;
        const char* b0 = Bg + (size_t)rowA0 * (K * 2) + kt * 64 + off0;
        const char* b1 = Bg + (size_t)rowA1 * (K * 2) + kt * 64 + off1;
        cp16(dA + rowA0 * 80 + off0, a0);
        cp16(dA + rowA1 * 80 + off1, a1);
        cp16(dB + rowA0 * 80 + off0, b0);
        cp16(dB + rowA1 * 80 + off1, b1);
        CP_COMMIT();
    };

    wmma::fragment<wmma::accumulator, 16, 16, 16, float> acc[4][2];
#pragma unroll
    for (int i = 0; i < 4; i++)
#pragma unroll
        for (int j = 0; j < 2; j++) wmma::fill_fragment(acc[i][j], 0.f);

    load_stage(0, 0);
    load_stage(1, 1);
    load_stage(2, 2);

    const int NKT = K / 32;   // 32
    for (int kt = 0; kt < NKT; kt++) {
        int cur = kt & 3;
        CP_WAIT2();
        __syncthreads();
        if (kt + 3 < NKT) load_stage(kt + 3, (kt + 3) & 3);
        else CP_COMMIT();
        const __nv_bfloat16* As = (const __nv_bfloat16*)(sA + cur * OUT_STAGE_B);
        const __nv_bfloat16* Bs = (const __nv_bfloat16*)(sB + cur * OUT_STAGE_B);
#pragma unroll
        for (int ks = 0; ks < 2; ks++) {
            wmma::fragment<wmma::matrix_a, 16, 16, 16, __nv_bfloat16, wmma::row_major> af[4];
            wmma::fragment<wmma::matrix_b, 16, 16, 16, __nv_bfloat16, wmma::col_major> bf[2];
#pragma unroll
            for (int i = 0; i < 4; i++)
                wmma::load_matrix_sync(af[i], As + (wm * 64 + i * 16) * 40 + ks * 16, 40);
#pragma unroll
            for (int j = 0; j < 2; j++)
                wmma::load_matrix_sync(bf[j], Bs + (wn * 32 + j * 16) * 40 + ks * 16, 40);
#pragma unroll
            for (int i = 0; i < 4; i++)
#pragma unroll
                for (int j = 0; j < 2; j++)
                    wmma::mma_sync(acc[i][j], af[i], bf[j], acc[i][j]);
        }
    }
    __syncthreads();

    // epilogue: stage per-warp 16x16 tiles, remap rows (t*64+b) -> out[(b*T+t)*V]
    float* stage = (float*)dyn;
    float* sp = stage + warp * 320;
#pragma unroll
    for (int i = 0; i < 4; i++) {
#pragma unroll
        for (int j = 0; j < 2; j++) {
            wmma::store_matrix_sync(sp, acc[i][j], 20, wmma::mem_row_major);
            __syncwarp();
            int gr0 = m0 + wm * 64 + i * 16;
            int gc0 = n0 + wn * 32 + j * 16;
            for (int e = lane; e < 256; e += 32) {
                int r = e >> 4, cc = e & 15;
                int gr = gr0 + r, gc = gc0 + cc;
                int bb = gr & 63, tt = gr >> 6;
                out[(size_t)(bb * Tsz + tt) * Vsz + gc] = sp[r * 20 + cc] + b_out[gc];
            }
            __syncwarp();
        }
    }
}

// ---------------- in-place log_softmax (float4) ----------------
__global__ __launch_bounds__(256) void k_logsoftmax(float* __restrict__ out) {
    int row = blockIdx.x;
    float4* p4 = (float4*)(out + (size_t)row * Vsz);
    const int N4 = Vsz / 4;
    int tid = threadIdx.x;
    float m = -1e30f, s = 0.f;
    for (int j = tid; j < N4; j += 256) {
        float4 v = p4[j];
        float vm = fmaxf(fmaxf(v.x, v.y), fmaxf(v.z, v.w));
        if (vm > m) { s = s * __expf(m - vm); m = vm; }
        s += __expf(v.x - m) + __expf(v.y - m) + __expf(v.z - m) + __expf(v.w - m);
    }
    __shared__ float sm[256], ss[256];
    sm[tid] = m; ss[tid] = s;
    __syncthreads();
    for (int o = 128; o > 0; o >>= 1) {
        if (tid < o) {
            float m2 = sm[tid + o], s2 = ss[tid + o];
            float mm = fmaxf(sm[tid], m2);
            ss[tid] = ss[tid] * __expf(sm[tid] - mm) + s2 * __expf(m2 - mm);
            sm[tid] = mm;
        }
        __syncthreads();
    }
    float L = sm[0] + logf(ss[0]);
    for (int j = tid; j < N4; j += 256) {
        float4 v = p4[j];
        v.x -= L; v.y -= L; v.z -= L; v.w -= L;
        p4[j] = v;
    }
}

// ---------------- launch ----------------
extern "C" void kernel_launch(void* const* d_in, const int* in_sizes, int n_in,
                              void* d_out, int out_size) {
    const float* enc_out = (const float*)d_in[0];
    const float* enc_hid = (const float*)d_in[1];
    const int*   target  = (const int*)d_in[2];
    const float* embedding = (const float*)d_in[3];
    const float* Wa  = (const float*)d_in[4];
    const float* ba  = (const float*)d_in[5];
    const float* Ua  = (const float*)d_in[6];
    const float* bu  = (const float*)d_in[7];
    const float* Va  = (const float*)d_in[8];
    // d_in[9] = bv : softmax shift-invariant, unused
    const float* W_ih = (const float*)d_in[10];
    const float* W_hh = (const float*)d_in[11];
    const float* b_ih = (const float*)d_in[12];
    const float* b_hh = (const float*)d_in[13];
    const float* W_out = (const float*)d_in[14];
    const float* b_out = (const float*)d_in[15];

    float* out = (float*)d_out;
    float* out_dec  = out;                                        // [B,T,V]
    float* out_hid  = out + (size_t)Bsz * Tsz * Vsz;              // [1,B,H]
    float* out_attn = out_hid + (size_t)Bsz * Hsz;                // [B,T,S]

    cudaFuncSetAttribute(k_gemm_out, cudaFuncAttributeMaxDynamicSharedMemorySize,
                         8 * OUT_STAGE_B);

    // launches 0..4: init (ncu -s 5 -c 1 then captures k_persist at index 5)
    k_round_all<<<1024, 256>>>(enc_out, Ua, Wa, W_hh, W_ih);
    k_embed_init<<<Tsz * Bsz + 256, 256>>>(target, embedding, enc_hid);
    k_wout_conv<<<2048, 256>>>(W_out);
    {
        dim3 grid(Hsz / 128, (Bsz * Ssz) / 64);   // 8 x 64
        k_gemm_keysu<<<grid, NTHR>>>();
    }
    {
        dim3 grid(3 * Hsz / 128, Tsz);            // 24 x 40
        k_gemm_giemb<<<grid, NTHR>>>();
    }

    // full recurrence in one launch (index 5)
    k_persist<<<NBLK, NTHR>>>(enc_out, Va, ba, bu, b_ih, b_hh, out_attn, out_hid);

    // output projection + log_softmax
    {
        dim3 grid(Vsz / 128, (Tsz * Bsz) / 128);  // 250 x 20
        k_gemm_out<<<grid, 256, 8 * OUT_STAGE_B>>>(b_out, out_dec);
    }
    k_logsoftmax<<<Tsz * Bsz, 256>>>(out_dec);
}

// round 9
// speedup vs baseline: 1.0922x; 1.0623x over previous
#include <cuda_runtime.h>
#include <cuda_bf16.h>
#include <mma.h>
#include <cstdint>

using namespace nvcuda;

#define Bsz 64
#define Ssz 64
#define Hsz 1024
#define Vsz 32000
#define Tsz 40
#define NBLK 148
#define NTHR 256

// ---------------- scratch ----------------
__device__ float g_keysU[Bsz * Ssz * Hsz];          // 16 MB (bias added in persist)
__device__ float g_emb[Tsz * Bsz * Hsz];            // 10 MB [t][b][h] (tf32-rounded)
__device__ float g_h[Bsz * Hsz];                    // exact fp32 hidden
__device__ float g_h32[Bsz * Hsz];                  // tf32-rounded copy for GEMMs
__device__ float g_q4[4][Bsz * Hsz];                // q split-K parts
__device__ float g_gh2[2][Bsz * 3 * Hsz];           // gh split-K parts (K=512 x2)
__device__ float g_gc4[4][Bsz * 3 * Hsz];           // gi ctx-half split-K parts
__device__ float g_giE[(size_t)Tsz * Bsz * 3 * Hsz];// 31.5 MB
__device__ float g_ctx[Bsz * Hsz];                  // tf32-rounded at store
__device__ __nv_bfloat16 g_hall[Tsz * Bsz * Hsz];   // 5 MB
__device__ __nv_bfloat16 g_wout[Vsz * Hsz];         // 65 MB
// tf32-RN pre-rounded operand copies
__device__ float g_enc32[Bsz * Ssz * Hsz];          // 16 MB
__device__ float g_Ua32[Hsz * Hsz];
__device__ float g_Wa32[Hsz * Hsz];
__device__ float g_Whh32[3 * Hsz * Hsz];
__device__ float g_Wih32[3 * Hsz * 2 * Hsz];
__device__ unsigned g_barcnt = 0;
__device__ unsigned g_bargen = 0;
// dependency channels: 0=q 1=ctx 2=d 3=gh 4=h
__device__ unsigned g_ccnt[8];
__device__ volatile unsigned g_cgen[8];
#define CH_Q 0
#define CH_CTX 1
#define CH_D 2
#define CH_GH 3
#define CH_H 4

// fast activations
__device__ __forceinline__ float tanh_fast(float x) {
    float y; asm("tanh.approx.f32 %0, %1;" : "=f"(y) : "f"(x)); return y;
}
__device__ __forceinline__ float ftanh(float x) {
    float e = __expf(2.f * x);
    return 1.f - __fdividef(2.f, e + 1.f);
}
__device__ __forceinline__ float fsigmoid(float x) {
    return __fdividef(1.f, 1.f + __expf(-x));
}
__device__ __forceinline__ float rnd32(float x) {   // tf32 round-to-nearest
    float y; asm("cvt.rna.tf32.f32 %0, %1;" : "=f"(y) : "f"(x)); return y;
}

// cp.async helpers
__device__ __forceinline__ void cp16(void* sdst, const void* gsrc) {
    unsigned s = (unsigned)__cvta_generic_to_shared(sdst);
    asm volatile("cp.async.cg.shared.global [%0], [%1], 16;\n" :: "r"(s), "l"(gsrc));
}
#define CP_COMMIT() asm volatile("cp.async.commit_group;\n")
#define CP_WAIT1()  asm volatile("cp.async.wait_group 1;\n")
#define CP_WAIT2()  asm volatile("cp.async.wait_group 2;\n")

// channel barrier primitives (block-granular; conditions on bx only)
__device__ __forceinline__ void ch_arrive(int ch, unsigned total, unsigned gen, int tid) {
    __syncthreads();                        // block's global writes issued
    if (tid == 0) {
        __threadfence();                    // publish
        unsigned old = atomicAdd(&g_ccnt[ch], 1u);
        if (old == total - 1) {
            g_ccnt[ch] = 0;
            __threadfence();
            g_cgen[ch] = gen;
        }
    }
}
__device__ __forceinline__ void ch_wait(int ch, unsigned gen, int tid) {
    if (tid == 0) {
        while (g_cgen[ch] < gen) __nanosleep(32);
        __threadfence();
    }
    __syncthreads();
}
__device__ __forceinline__ void ch_wait2(int c0, int c1, unsigned gen, int tid) {
    if (tid == 0) {
        while (g_cgen[c0] < gen) __nanosleep(32);
        while (g_cgen[c1] < gen) __nanosleep(32);
        __threadfence();
    }
    __syncthreads();
}

// ---------------- init kernels ----------------
__global__ void k_round_all(const float* __restrict__ enc, const float* __restrict__ Ua,
                            const float* __restrict__ Wa, const float* __restrict__ Whh,
                            const float* __restrict__ Wih) {
    const int nEnc = Bsz * Ssz * Hsz / 4;
    const int nUa  = Hsz * Hsz / 4;
    const int nWhh = 3 * Hsz * Hsz / 4;
    const int nWih = 3 * Hsz * 2 * Hsz / 4;
    const int e0 = nEnc, e1 = e0 + nUa, e2 = e1 + nUa, e3 = e2 + nWhh, e4 = e3 + nWih;
    for (int i = blockIdx.x * blockDim.x + threadIdx.x; i < e4; i += gridDim.x * blockDim.x) {
        const float4* src; float4* dst;
        if (i < e0)      { src = (const float4*)enc + i;        dst = (float4*)g_enc32 + i; }
        else if (i < e1) { src = (const float4*)Ua + (i - e0);  dst = (float4*)g_Ua32 + (i - e0); }
        else if (i < e2) { src = (const float4*)Wa + (i - e1);  dst = (float4*)g_Wa32 + (i - e1); }
        else if (i < e3) { src = (const float4*)Whh + (i - e2); dst = (float4*)g_Whh32 + (i - e2); }
        else             { src = (const float4*)Wih + (i - e3); dst = (float4*)g_Wih32 + (i - e3); }
        float4 v = *src;
        v.x = rnd32(v.x); v.y = rnd32(v.y); v.z = rnd32(v.z); v.w = rnd32(v.w);
        *dst = v;
    }
}

__global__ void k_embed_init(const int* __restrict__ target, const float* __restrict__ emb,
                             const float* __restrict__ eh) {
    int bx = blockIdx.x;
    if (bx < Tsz * Bsz) {
        int t = bx / Bsz, b = bx % Bsz;
        int tok = (t == 0) ? 0 : target[b * Tsz + t - 1];
        const float4* src = (const float4*)(emb + (size_t)tok * Hsz);
        float4* dst = (float4*)(g_emb + ((size_t)t * Bsz + b) * Hsz);
        for (int j = threadIdx.x; j < Hsz / 4; j += blockDim.x) {
            float4 v = src[j];
            v.x = rnd32(v.x); v.y = rnd32(v.y); v.z = rnd32(v.z); v.w = rnd32(v.w);
            dst[j] = v;
        }
    } else {
        int i = (bx - Tsz * Bsz) * 256 + threadIdx.x;
        if (i < Bsz * Hsz) { g_h[i] = eh[i]; g_h32[i] = rnd32(eh[i]); }
    }
}

__global__ void k_wout_conv(const float* __restrict__ W) {
    int n4 = Vsz * Hsz / 4;
    for (int i = blockIdx.x * blockDim.x + threadIdx.x; i < n4; i += gridDim.x * blockDim.x) {
        float4 v = ((const float4*)W)[i];
        ((__nv_bfloat162*)g_wout)[2 * i]     = __floats2bfloat162_rn(v.x, v.y);
        ((__nv_bfloat162*)g_wout)[2 * i + 1] = __floats2bfloat162_rn(v.z, v.w);
    }
}

// ---------------- tf32 64x128 tile GEMM, cp.async 3-stage, BK=16 ----------------
__device__ __forceinline__ void gemm64x128(const float* __restrict__ A, int lda,
                                           const float* __restrict__ B, int ldb,
                                           float* __restrict__ C, int ldc,
                                           int kiters, float* sbuf) {
    float (*As)[64][20]  = (float(*)[64][20])sbuf;
    float (*Bs)[128][20] = (float(*)[128][20])(sbuf + 3 * 64 * 20);
    int tid = threadIdx.x;
    int ra = tid >> 2, ca = (tid & 3) << 2;
    int rb = tid >> 1, cb = (tid & 1) << 3;
    int warp = tid >> 5, wm = warp >> 2, wn = warp & 3;

    const float* Ap = A + (size_t)ra * lda + ca;
    const float* Bp = B + (size_t)rb * ldb + cb;

    wmma::fragment<wmma::accumulator, 16, 16, 8, float> acc[2][2];
#pragma unroll
    for (int i = 0; i < 2; i++)
#pragma unroll
        for (int j = 0; j < 2; j++) wmma::fill_fragment(acc[i][j], 0.f);

#pragma unroll
    for (int s = 0; s < 2; s++) {
        if (s < kiters) {
            cp16(&As[s][ra][ca], Ap + s * 16);
            cp16(&Bs[s][rb][cb], Bp + s * 16);
            cp16(&Bs[s][rb][cb + 4], Bp + s * 16 + 4);
        }
        CP_COMMIT();
    }

    int stg = 2;
    for (int it = 0; it < kiters; it++) {
        int cur = it % 3;
        CP_WAIT1();
        __syncthreads();
        if (it + 2 < kiters) {
            cp16(&As[stg][ra][ca], Ap + (it + 2) * 16);
            cp16(&Bs[stg][rb][cb], Bp + (it + 2) * 16);
            cp16(&Bs[stg][rb][cb + 4], Bp + (it + 2) * 16 + 4);
        }
        CP_COMMIT();
        stg++; if (stg == 3) stg = 0;
#pragma unroll
        for (int ks = 0; ks < 2; ks++) {
            wmma::fragment<wmma::matrix_a, 16, 16, 8, wmma::precision::tf32, wmma::row_major> af0, af1;
            wmma::fragment<wmma::matrix_b, 16, 16, 8, wmma::precision::tf32, wmma::col_major> bf0, bf1;
            wmma::load_matrix_sync(af0, &As[cur][wm * 32][ks * 8], 20);
            wmma::load_matrix_sync(af1, &As[cur][wm * 32 + 16][ks * 8], 20);
            wmma::load_matrix_sync(bf0, &Bs[cur][wn * 32][ks * 8], 20);
            wmma::load_matrix_sync(bf1, &Bs[cur][wn * 32 + 16][ks * 8], 20);
            wmma::mma_sync(acc[0][0], af0, bf0, acc[0][0]);
            wmma::mma_sync(acc[0][1], af0, bf1, acc[0][1]);
            wmma::mma_sync(acc[1][0], af1, bf0, acc[1][0]);
            wmma::mma_sync(acc[1][1], af1, bf1, acc[1][1]);
        }
    }
    __syncthreads();
#pragma unroll
    for (int i = 0; i < 2; i++)
#pragma unroll
        for (int j = 0; j < 2; j++)
            wmma::store_matrix_sync(C + (size_t)(wm * 32 + i * 16) * ldc + wn * 32 + j * 16,
                                    acc[i][j], ldc, wmma::mem_row_major);
}

// merged precompute: keysU (512 tiles) + giE (960 tiles) in one launch
__global__ __launch_bounds__(NTHR, 2) void k_gemm_pre() {
    __shared__ float sbuf[11520];
    int bx = blockIdx.x;
    if (bx < 512) {
        int nt = bx & 7, mt = bx >> 3;
        int m0 = mt * 64, n0 = nt * 128;
        gemm64x128(g_enc32 + (size_t)m0 * Hsz, Hsz, g_Ua32 + (size_t)n0 * Hsz, Hsz,
                   g_keysU + (size_t)m0 * Hsz + n0, Hsz, 64, sbuf);
    } else {
        int idx = bx - 512;
        int nt = idx % 24, t = idx / 24;
        int n0 = nt * 128;
        gemm64x128(g_emb + (size_t)t * Bsz * Hsz, Hsz,
                   g_Wih32 + (size_t)n0 * (2 * Hsz), 2 * Hsz,
                   g_giE + (size_t)t * Bsz * 3 * Hsz + n0, 3 * Hsz, 64, sbuf);
    }
}

// ---------------- persistent recurrence kernel ----------------
__global__ __launch_bounds__(NTHR, 1) void k_persist(
    const float* __restrict__ enc, const float* __restrict__ Va,
    const float* __restrict__ ba, const float* __restrict__ bu,
    const float* __restrict__ b_ih, const float* __restrict__ b_hh,
    float* __restrict__ out_attn, float* __restrict__ out_hid)
{
    __shared__ float sbuf[11520];
    __shared__ unsigned s_gen0;
    int tid = threadIdx.x;
    int bx = blockIdx.x;
    if (tid == 0) s_gen0 = *((volatile unsigned*)&g_bargen);
    __syncthreads();
    unsigned gen = s_gen0;

    auto gbar = [&]() {
        gen++;
        __syncthreads();
        if (tid == 0) {
            __threadfence();
            unsigned a = atomicAdd(&g_barcnt, 1u);
            if (a == NBLK - 1) {
                g_barcnt = 0;
                __threadfence();
                *((volatile unsigned*)&g_bargen) = gen;
            } else {
                while (*((volatile unsigned*)&g_bargen) != gen) __nanosleep(32);
                __threadfence();
            }
        }
        __syncthreads();
    };

    // pre-phase: fold attention biases into keysU; reset channels
    for (int i = bx * NTHR + tid; i < Bsz * Ssz * Hsz; i += NBLK * NTHR) {
        int n = i & (Hsz - 1);
        g_keysU[i] += ba[n] + bu[n];
    }
    gbar();
    if (bx == 0 && tid == 0) {
#pragma unroll
        for (int c = 0; c < 8; c++) { g_ccnt[c] = 0; g_cgen[c] = 0; }
    }
    gbar();

    for (int t = 0; t < Tsz; t++) {
        unsigned g = (unsigned)t + 1;

        // ---- q: blocks 0-31 (8 n-tiles x split-K4, K=256) ----
        if (bx < 32) {
            ch_wait(CH_H, (unsigned)t, tid);
            int jt = bx >> 2, kh = bx & 3, n0 = jt * 128;
            gemm64x128(g_h32 + kh * 256, Hsz,
                       g_Wa32 + (size_t)n0 * Hsz + kh * 256, Hsz,
                       g_q4[kh] + n0, Hsz, 16, sbuf);
            ch_arrive(CH_Q, 32, g, tid);
        }

        // ---- gh: blocks 100-147 (24 n-tiles x split-K2, K=512), overlaps BC/D ----
        if (bx >= 100) {
            ch_wait(CH_H, (unsigned)t, tid);
            int idx = bx - 100, jt = idx >> 1, kh = idx & 1, n0 = jt * 128;
            gemm64x128(g_h32 + kh * 512, Hsz,
                       g_Whh32 + (size_t)n0 * Hsz + kh * 512, Hsz,
                       g_gh2[kh] + n0, 3 * Hsz, 32, sbuf);
            ch_arrive(CH_GH, 48, g, tid);
        }

        // ---- BC: scores + softmax + ctx, blocks 0-63 ----
        if (bx < 64) {
            ch_wait(CH_Q, g, tid);
            int b = bx;
            float* qs = sbuf;
            float* va = sbuf + 1024;
            float* sc = sbuf + 2048;
            float* ws = sbuf + 2112;
            for (int j = tid; j < Hsz; j += NTHR) {
                qs[j] = g_q4[0][b * Hsz + j] + g_q4[1][b * Hsz + j]
                      + g_q4[2][b * Hsz + j] + g_q4[3][b * Hsz + j];
                va[j] = Va[j];
            }
            __syncthreads();
            int w = tid >> 5, lane = tid & 31;
#pragma unroll
            for (int si = 0; si < 8; si++) {
                int s = w * 8 + si;
                const float* kp = g_keysU + (size_t)(b * Ssz + s) * Hsz;
                float acc = 0.f;
#pragma unroll 8
                for (int jj = 0; jj < 32; jj++) {
                    int j = lane + jj * 32;
                    acc += va[j] * tanh_fast(qs[j] + kp[j]);
                }
#pragma unroll
                for (int o = 16; o > 0; o >>= 1) acc += __shfl_xor_sync(0xffffffffu, acc, o);
                if (lane == 0) sc[s] = acc;
            }
            __syncthreads();
            if (w == 0) {
                float v0 = sc[lane], v1 = sc[lane + 32];
                float m = fmaxf(v0, v1);
#pragma unroll
                for (int o = 16; o > 0; o >>= 1) m = fmaxf(m, __shfl_xor_sync(0xffffffffu, m, o));
                float e0 = __expf(v0 - m), e1 = __expf(v1 - m);
                float ssum = e0 + e1;
#pragma unroll
                for (int o = 16; o > 0; o >>= 1) ssum += __shfl_xor_sync(0xffffffffu, ssum, o);
                float inv = __fdividef(1.f, ssum);
                ws[lane] = e0 * inv;
                ws[lane + 32] = e1 * inv;
            }
            __syncthreads();
            if (tid < Ssz) out_attn[(size_t)b * Tsz * Ssz + t * Ssz + tid] = ws[tid];
            float c0 = 0.f, c1 = 0.f, c2 = 0.f, c3 = 0.f;
            const float* ep = enc + (size_t)b * Ssz * Hsz + tid;
#pragma unroll 4
            for (int s = 0; s < Ssz; s++) {
                float wv = ws[s];
                const float* row = ep + (size_t)s * Hsz;
                c0 += wv * row[0];
                c1 += wv * row[256];
                c2 += wv * row[512];
                c3 += wv * row[768];
            }
            g_ctx[b * Hsz + tid]       = rnd32(c0);
            g_ctx[b * Hsz + tid + 256] = rnd32(c1);
            g_ctx[b * Hsz + tid + 512] = rnd32(c2);
            g_ctx[b * Hsz + tid + 768] = rnd32(c3);
            ch_arrive(CH_CTX, 64, g, tid);
        }

        // ---- D: gi_ctx = ctx @ W_ih[:, H:2H]^T, blocks 0-95 (24 n-tiles x split-K4) ----
        if (bx < 96) {
            ch_wait(CH_CTX, g, tid);
            int jt = bx >> 2, kh = bx & 3, n0 = jt * 128;
            gemm64x128(g_ctx + kh * 256, Hsz,
                       g_Wih32 + (size_t)n0 * (2 * Hsz) + Hsz + kh * 256, 2 * Hsz,
                       g_gc4[kh] + n0, 3 * Hsz, 16, sbuf);
            ch_arrive(CH_D, 96, g, tid);
        }

        // ---- E: gates + h update, all blocks ----
        ch_wait2(CH_D, CH_GH, g, tid);
        {
            const float* giE = g_giE + (size_t)t * Bsz * 3 * Hsz;
            for (int i = bx * NTHR + tid; i < Bsz * Hsz; i += NBLK * NTHR) {
                int b = i >> 10, j = i & (Hsz - 1);
                size_t base3 = (size_t)b * 3 * Hsz;
                float ir = giE[base3 + j] + b_ih[j];
                float iz = giE[base3 + Hsz + j] + b_ih[Hsz + j];
                float in = giE[base3 + 2 * Hsz + j] + b_ih[2 * Hsz + j];
#pragma unroll
                for (int kh = 0; kh < 4; kh++) {
                    ir += g_gc4[kh][base3 + j];
                    iz += g_gc4[kh][base3 + Hsz + j];
                    in += g_gc4[kh][base3 + 2 * Hsz + j];
                }
                float hr = b_hh[j]           + g_gh2[0][base3 + j]           + g_gh2[1][base3 + j];
                float hz = b_hh[Hsz + j]     + g_gh2[0][base3 + Hsz + j]     + g_gh2[1][base3 + Hsz + j];
                float hn = b_hh[2 * Hsz + j] + g_gh2[0][base3 + 2 * Hsz + j] + g_gh2[1][base3 + 2 * Hsz + j];
                float rr = fsigmoid(ir + hr);
                float zz = fsigmoid(iz + hz);
                float nn = ftanh(in + rr * hn);
                float hp = g_h[i];
                float hnew = (1.f - zz) * nn + zz * hp;
                g_h[i] = hnew;
                g_h32[i] = rnd32(hnew);
                g_hall[((size_t)t * Bsz + b) * Hsz + j] = __float2bfloat16(hnew);
            }
        }
        ch_arrive(CH_H, NBLK, g, tid);
    }

    // final hidden copy: same striping as E, so each block copies its own values
    for (int i = bx * NTHR + tid; i < Bsz * Hsz; i += NBLK * NTHR)
        out_hid[i] = g_h[i];
}

// ---------------- output projection: logits = Hall @ Wout^T + b_out ----------------
#define OUT_STAGE_B 10240
__global__ __launch_bounds__(256, 2) void k_gemm_out(const float* __restrict__ b_out,
                                                     float* __restrict__ out) {
    extern __shared__ char dyn[];
    char* sA = dyn;
    char* sB = dyn + 4 * OUT_STAGE_B;
    const int K = Hsz;
    int m0 = blockIdx.y * 128, n0 = blockIdx.x * 128;
    int tid = threadIdx.x;
    int warp = tid >> 5, lane = tid & 31;
    int wm = warp >> 2, wn = warp & 3;

    const char* Ag = (const char*)(g_hall + (size_t)m0 * K);
    const char* Bg = (const char*)(g_wout + (size_t)n0 * K);

    int c0 = tid * 2;
    int rowA0 = c0 >> 2, off0 = (c0 & 3) * 16;
    int rowA1 = (c0 + 1) >> 2, off1 = ((c0 + 1) & 3) * 16;

    auto load_stage = [&](int kt, int s) {
        char* dA = sA + s * OUT_STAGE_B;
        char* dB = sB + s * OUT_STAGE_B;
        const char* a0 = Ag + (size_t)rowA0 * (K * 2) + kt * 64 + off0;
        const char* a1 = Ag + (size_t)rowA1 * (K * 2) + kt * 64 + off1;
        const char* b0 = Bg + (size_t)rowA0 * (K * 2) + kt * 64 + off0;
        const char* b1 = Bg + (size_t)rowA1 * (K * 2) + kt * 64 + off1;
        cp16(dA + rowA0 * 80 + off0, a0);
        cp16(dA + rowA1 * 80 + off1, a1);
        cp16(dB + rowA0 * 80 + off0, b0);
        cp16(dB + rowA1 * 80 + off1, b1);
        CP_COMMIT();
    };

    wmma::fragment<wmma::accumulator, 16, 16, 16, float> acc[4][2];
#pragma unroll
    for (int i = 0; i < 4; i++)
#pragma unroll
        for (int j = 0; j < 2; j++) wmma::fill_fragment(acc[i][j], 0.f);

    load_stage(0, 0);
    load_stage(1, 1);
    load_stage(2, 2);

    const int NKT = K / 32;
    for (int kt = 0; kt < NKT; kt++) {
        int cur = kt & 3;
        CP_WAIT2();
        __syncthreads();
        if (kt + 3 < NKT) load_stage(kt + 3, (kt + 3) & 3);
        else CP_COMMIT();
        const __nv_bfloat16* As = (const __nv_bfloat16*)(sA + cur * OUT_STAGE_B);
        const __nv_bfloat16* Bs = (const __nv_bfloat16*)(sB + cur * OUT_STAGE_B);
#pragma unroll
        for (int ks = 0; ks < 2; ks++) {
            wmma::fragment<wmma::matrix_a, 16, 16, 16, __nv_bfloat16, wmma::row_major> af[4];
            wmma::fragment<wmma::matrix_b, 16, 16, 16, __nv_bfloat16, wmma::col_major> bf[2];
#pragma unroll
            for (int i = 0; i < 4; i++)
                wmma::load_matrix_sync(af[i], As + (wm * 64 + i * 16) * 40 + ks * 16, 40);
#pragma unroll
            for (int j = 0; j < 2; j++)
                wmma::load_matrix_sync(bf[j], Bs + (wn * 32 + j * 16) * 40 + ks * 16, 40);
#pragma unroll
            for (int i = 0; i < 4; i++)
#pragma unroll
                for (int j = 0; j < 2; j++)
                    wmma::mma_sync(acc[i][j], af[i], bf[j], acc[i][j]);
        }
    }
    __syncthreads();

    float* stage = (float*)dyn;
    float* sp = stage + warp * 320;
#pragma unroll
    for (int i = 0; i < 4; i++) {
#pragma unroll
        for (int j = 0; j < 2; j++) {
            wmma::store_matrix_sync(sp, acc[i][j], 20, wmma::mem_row_major);
            __syncwarp();
            int gr0 = m0 + wm * 64 + i * 16;
            int gc0 = n0 + wn * 32 + j * 16;
            for (int e = lane; e < 256; e += 32) {
                int r = e >> 4, cc = e & 15;
                int gr = gr0 + r, gc = gc0 + cc;
                int bb = gr & 63, tt = gr >> 6;
                out[(size_t)(bb * Tsz + tt) * Vsz + gc] = sp[r * 20 + cc] + b_out[gc];
            }
            __syncwarp();
        }
    }
}

// ---------------- in-place log_softmax (float4) ----------------
__global__ __launch_bounds__(256) void k_logsoftmax(float* __restrict__ out) {
    int row = blockIdx.x;
    float4* p4 = (float4*)(out + (size_t)row * Vsz);
    const int N4 = Vsz / 4;
    int tid = threadIdx.x;
    float m = -1e30f, s = 0.f;
    for (int j = tid; j < N4; j += 256) {
        float4 v = p4[j];
        float vm = fmaxf(fmaxf(v.x, v.y), fmaxf(v.z, v.w));
        if (vm > m) { s = s * __expf(m - vm); m = vm; }
        s += __expf(v.x - m) + __expf(v.y - m) + __expf(v.z - m) + __expf(v.w - m);
    }
    __shared__ float sm[256], ss[256];
    sm[tid] = m; ss[tid] = s;
    __syncthreads();
    for (int o = 128; o > 0; o >>= 1) {
        if (tid < o) {
            float m2 = sm[tid + o], s2 = ss[tid + o];
            float mm = fmaxf(sm[tid], m2);
            ss[tid] = ss[tid] * __expf(sm[tid] - mm) + s2 * __expf(m2 - mm);
            sm[tid] = mm;
        }
        __syncthreads();
    }
    float L = sm[0] + logf(ss[0]);
    for (int j = tid; j < N4; j += 256) {
        float4 v = p4[j];
        v.x -= L; v.y -= L; v.z -= L; v.w -= L;
        p4[j] = v;
    }
}

// ---------------- launch ----------------
extern "C" void kernel_launch(void* const* d_in, const int* in_sizes, int n_in,
                              void* d_out, int out_size) {
    const float* enc_out = (const float*)d_in[0];
    const float* enc_hid = (const float*)d_in[1];
    const int*   target  = (const int*)d_in[2];
    const float* embedding = (const float*)d_in[3];
    const float* Wa  = (const float*)d_in[4];
    const float* ba  = (const float*)d_in[5];
    const float* Ua  = (const float*)d_in[6];
    const float* bu  = (const float*)d_in[7];
    const float* Va  = (const float*)d_in[8];
    // d_in[9] = bv : softmax shift-invariant, unused
    const float* W_ih = (const float*)d_in[10];
    const float* W_hh = (const float*)d_in[11];
    const float* b_ih = (const float*)d_in[12];
    const float* b_hh = (const float*)d_in[13];
    const float* W_out = (const float*)d_in[14];
    const float* b_out = (const float*)d_in[15];

    float* out = (float*)d_out;
    float* out_dec  = out;                                        // [B,T,V]
    float* out_hid  = out + (size_t)Bsz * Tsz * Vsz;              // [1,B,H]
    float* out_attn = out_hid + (size_t)Bsz * Hsz;                // [B,T,S]

    cudaFuncSetAttribute(k_gemm_out, cudaFuncAttributeMaxDynamicSharedMemorySize,
                         8 * OUT_STAGE_B);

    // init
    k_round_all<<<1024, 256>>>(enc_out, Ua, Wa, W_hh, W_ih);
    k_embed_init<<<Tsz * Bsz + 256, 256>>>(target, embedding, enc_hid);
    k_wout_conv<<<2048, 256>>>(W_out);
    k_gemm_pre<<<512 + 960, NTHR>>>();

    // full recurrence in one launch
    k_persist<<<NBLK, NTHR>>>(enc_out, Va, ba, bu, b_ih, b_hh, out_attn, out_hid);

    // output projection + log_softmax
    {
        dim3 grid(Vsz / 128, (Tsz * Bsz) / 128);  // 250 x 20
        k_gemm_out<<<grid, 256, 8 * OUT_STAGE_B>>>(b_out, out_dec);
    }
    k_logsoftmax<<<Tsz * Bsz, 256>>>(out_dec);
}